// round 8
// baseline (speedup 1.0000x reference)
#include <cuda_runtime.h>
#include <cuda_bf16.h>
#include <math.h>
#include <stdint.h>

// Problem constants (fixed shapes)
#define N_SPOTS 10000
#define D_LAT   128
#define D_IN    3000
#define KNN_K   10
#define SCALE   6
#define BN_EPS  1e-4f

// KNN grid
#define GRID_D  40
#define CSZ     2.5f
#define INV_CSZ 0.4f
#define NCELLS  (GRID_D * GRID_D)
#define SLACK   0.5f

#define INF_F __int_as_float(0x7f800000)

// ---------------- scratch (device globals; no allocation allowed) -------------
__device__ int    g_idx[N_SPOTS * KNN_K];
__device__ int    g_cnt[NCELLS];
__device__ int    g_cur[NCELLS];
__device__ __align__(8)  int2   g_range[NCELLS];      // (start, count)
__device__ __align__(16) float4 g_sp4[N_SPOTS];       // (x, y, idx-bits, 0)
__device__ __align__(16) float g_G[D_LAT * D_LAT];    // Z^T Z
__device__ __align__(16) float g_s[D_LAT];            // col-sum of Z
__device__ __align__(16) float g_mu[D_IN];
__device__ __align__(16) float g_rs[D_IN];
// pre-split bf16 hi/lo operands (packed bf16x2 per k-pair), n-major for W
__device__ __align__(16) uint32_t g_zh[(size_t)N_SPOTS * 64];   // [row][kp]
__device__ __align__(16) uint32_t g_zl[(size_t)N_SPOTS * 64];
__device__ __align__(16) uint32_t g_bh[(size_t)D_IN * 64];      // [n][kp]
__device__ __align__(16) uint32_t g_bl[(size_t)D_IN * 64];

// lexicographic (d2, idx) compare: matches jax.lax.top_k stable tie-break
__device__ __forceinline__ bool lexless(float d1, int j1, float d2, int j2) {
    return (d1 < d2) || (d1 == d2 && j1 < j2);
}

__device__ __forceinline__ int cell_x(float x) {
    int c = (int)(x * INV_CSZ);
    return min(GRID_D - 1, max(0, c));
}

__device__ __forceinline__ void split_bf(float v, __nv_bfloat16& h, __nv_bfloat16& l) {
    h = __float2bfloat16_rn(v);
    l = __float2bfloat16_rn(v - __bfloat162float(h));
}

__device__ __forceinline__ uint32_t pack2(__nv_bfloat16 a, __nv_bfloat16 b) {
    __nv_bfloat162 t; t.x = a; t.y = b;     // .x = low 16 bits = lower-k element
    return *reinterpret_cast<uint32_t*>(&t);
}

// ----------------------------- KNN: build grid ---------------------------------
__global__ void knn_count(const float2* __restrict__ sp) {
    const int i = blockIdx.x * 256 + threadIdx.x;
    if (i >= N_SPOTS) return;
    const float2 s = sp[i];
    atomicAdd(&g_cnt[cell_x(s.y) * GRID_D + cell_x(s.x)], 1);
}

// single-warp exclusive scan over 1600 cells
__global__ void knn_scan() {
    const int lane = threadIdx.x;           // 32 threads
    const int CH = NCELLS / 32;             // 50
    const int base = lane * CH;
    int s = 0;
    for (int k = 0; k < CH; k++) s += g_cnt[base + k];
    int inc = s;
#pragma unroll
    for (int o = 1; o < 32; o <<= 1) {
        int v = __shfl_up_sync(0xffffffffu, inc, o);
        if (lane >= o) inc += v;
    }
    int run = inc - s;
    for (int k = 0; k < CH; k++) {
        const int c = g_cnt[base + k];
        g_range[base + k] = make_int2(run, c);
        run += c;
    }
}

__global__ void knn_scatter(const float2* __restrict__ sp) {
    const int i = blockIdx.x * 256 + threadIdx.x;
    if (i >= N_SPOTS) return;
    const float2 s = sp[i];
    const int c = cell_x(s.y) * GRID_D + cell_x(s.x);
    const int dst = g_range[c].x + atomicAdd(&g_cur[c], 1);
    g_sp4[dst] = make_float4(s.x, s.y, __int_as_float(i), 0.0f);
}

// ----------------------------- KNN: ring search --------------------------------
// d2 BIT-EXACT vs reference (XLA lowers the K=2 dot without fma):
//   sq = rn(rn(x*x) + rn(y*y));  dot = rn(rn(xi*xj) + rn(yi*yj))
//   d2 = rn(rn(sqi + sqj) - 2*dot)
__device__ __forceinline__ void proc_cell(int c, int i, float mx, float my, float sqi,
                                          float* dd, int* jj,
                                          float& wd, int& wj, int& ws) {
    const int2 rg = g_range[c];
    const int t1 = rg.x + rg.y;
    for (int t = rg.x; t < t1; t++) {
        const float4 s = g_sp4[t];
        const int j = __float_as_int(s.z);
        if (j == i) continue;
        const float sqj = __fadd_rn(__fmul_rn(s.x, s.x), __fmul_rn(s.y, s.y));
        const float dot = __fadd_rn(__fmul_rn(mx, s.x), __fmul_rn(my, s.y));
        const float d2  = __fadd_rn(__fadd_rn(sqi, sqj), __fmul_rn(-2.0f, dot));
        if (lexless(d2, j, wd, wj)) {
#pragma unroll
            for (int k = 0; k < KNN_K; k++) if (k == ws) { dd[k] = d2; jj[k] = j; }
            wd = dd[0]; wj = jj[0]; ws = 0;
#pragma unroll
            for (int k = 1; k < KNN_K; k++)
                if (lexless(wd, wj, dd[k], jj[k])) { wd = dd[k]; wj = jj[k]; ws = k; }
        }
    }
}

__global__ void knn_search(int* __restrict__ idx_out) {
    const int p = blockIdx.x * 64 + threadIdx.x;
    if (p >= N_SPOTS) return;
    const float4 me = g_sp4[p];
    const int i = __float_as_int(me.z);
    const float sqi = __fadd_rn(__fmul_rn(me.x, me.x), __fmul_rn(me.y, me.y));
    const int cx = cell_x(me.x), cy = cell_x(me.y);

    float dd[KNN_K]; int jj[KNN_K];
#pragma unroll
    for (int k = 0; k < KNN_K; k++) { dd[k] = INF_F; jj[k] = 0x7fffffff; }
    float wd = INF_F; int wj = 0x7fffffff; int ws = 0;

    for (int R = 0; R <= GRID_D; R++) {
        if (R >= 2) {
            const float b = (float)(R - 1) * CSZ;
            if (wd + SLACK < b * b) break;
        }
        const int x0 = max(0, cx - R), x1 = min(GRID_D - 1, cx + R);
        const int y0 = max(0, cy - R), y1 = min(GRID_D - 1, cy + R);
        for (int yy = y0; yy <= y1; yy++) {
            if (yy == cy - R || yy == cy + R) {
                for (int xx = x0; xx <= x1; xx++)
                    proc_cell(yy * GRID_D + xx, i, me.x, me.y, sqi, dd, jj, wd, wj, ws);
            } else {
                if (cx - R >= 0)     proc_cell(yy * GRID_D + cx - R, i, me.x, me.y, sqi, dd, jj, wd, wj, ws);
                if (cx + R < GRID_D) proc_cell(yy * GRID_D + cx + R, i, me.x, me.y, sqi, dd, jj, wd, wj, ws);
            }
        }
    }
#pragma unroll
    for (int k = 0; k < KNN_K; k++) idx_out[i * KNN_K + k] = jj[k];
}

// --------------------------- aggregation (+ z bf16 split) ----------------------
__global__ void agg_kernel(const float* __restrict__ x,
                           const float* __restrict__ xn,
                           float* __restrict__ z_out,
                           float* __restrict__ hr_out) {
    const int i   = blockIdx.x;
    const int tid = threadIdx.x;          // 0..127
    const int lane = tid & 31, wrp = tid >> 5;

    __shared__ int   nb[KNN_K];
    __shared__ float red[4][KNN_K];
    __shared__ float neg_mean[KNN_K];

    if (tid < KNN_K) nb[tid] = g_idx[i * KNN_K + tid];
    __syncthreads();

    const float xi = x[(size_t)i * D_LAT + tid];
    float xv[KNN_K];
    float fd[KNN_K];
#pragma unroll
    for (int k = 0; k < KNN_K; k++) {
        const float v = x[(size_t)nb[k] * D_LAT + tid];
        xv[k] = v;
        const float d = v - xi;
        fd[k] = d * d;
    }
#pragma unroll
    for (int k = 0; k < KNN_K; k++) {
        float v = fd[k];
#pragma unroll
        for (int o = 16; o > 0; o >>= 1) v += __shfl_xor_sync(0xffffffffu, v, o);
        if (lane == 0) red[wrp][k] = v;
    }
    __syncthreads();
    if (tid < KNN_K) {
        const float s = red[0][tid] + red[1][tid] + red[2][tid] + red[3][tid];
        neg_mean[tid] = -(s * (1.0f / 128.0f));
    }
    __syncthreads();

    float m = neg_mean[0];
#pragma unroll
    for (int k = 1; k < KNN_K; k++) m = fmaxf(m, neg_mean[k]);
    float e[KNN_K], se = 0.0f;
#pragma unroll
    for (int k = 0; k < KNN_K; k++) { e[k] = expf(neg_mean[k] - m); se += e[k]; }
    float w[KNN_K];
#pragma unroll
    for (int k = 0; k < KNN_K; k++) w[k] = e[k] / se;

    float acc = 0.0f;
#pragma unroll
    for (int k = 0; k < KNN_K; k++) acc = __fmaf_rn(w[k], xv[k], acc);
    z_out[(size_t)i * D_LAT + tid] = acc;

    // bf16 hi/lo split of z, packed per k-pair (even lane packs tid & tid+1)
    const float accn = __shfl_down_sync(0xffffffffu, acc, 1);
    if ((tid & 1) == 0) {
        __nv_bfloat16 h0, l0, h1, l1;
        split_bf(acc,  h0, l0);
        split_bf(accn, h1, l1);
        g_zh[(size_t)i * 64 + (tid >> 1)] = pack2(h0, h1);
        g_zl[(size_t)i * 64 + (tid >> 1)] = pack2(l0, l1);
    }

#pragma unroll
    for (int s = 0; s < SCALE; s++) {
        float a = 0.0f;
#pragma unroll
        for (int k = 0; k < KNN_K; k++)
            a = __fmaf_rn(w[k], xn[((size_t)s * N_SPOTS + nb[k]) * D_LAT + tid], a);
        hr_out[(size_t)i * (SCALE * D_LAT) + s * D_LAT + tid] = a;
    }
}

// --------------------------- W bf16 split (n-major) ----------------------------
__global__ void split_w(const float* __restrict__ W) {
    const int idx = blockIdx.x * 256 + threadIdx.x;     // n * 64 + kp
    if (idx >= D_IN * 64) return;
    const int n = idx >> 6, kp = idx & 63;
    const float v0 = W[(size_t)(2 * kp)     * D_IN + n];
    const float v1 = W[(size_t)(2 * kp + 1) * D_IN + n];
    __nv_bfloat16 h0, l0, h1, l1;
    split_bf(v0, h0, l0);
    split_bf(v1, h1, l1);
    g_bh[idx] = pack2(h0, h1);
    g_bl[idx] = pack2(l0, l1);
}

// --------------------------- Gram: G = Z^T Z, s = colsum(Z) --------------------
#define GRAM_BLOCKS 80
__global__ void __launch_bounds__(256) gram_kernel(const float* __restrict__ z) {
    __shared__ float zrow[D_LAT];
    const int tid = threadIdx.x;
    const int i_own = tid >> 1;
    const int jb    = (tid & 1) * 64;

    float acc[64];
#pragma unroll
    for (int q = 0; q < 64; q++) acc[q] = 0.0f;
    float s_loc = 0.0f;

    for (int m = blockIdx.x; m < N_SPOTS; m += GRAM_BLOCKS) {
        if (tid < D_LAT) zrow[tid] = z[(size_t)m * D_LAT + tid];
        __syncthreads();
        const float zi = zrow[i_own];
#pragma unroll
        for (int q = 0; q < 64; q++) acc[q] = __fmaf_rn(zi, zrow[jb + q], acc[q]);
        if (tid < D_LAT) s_loc += zrow[tid];
        __syncthreads();
    }
#pragma unroll
    for (int q = 0; q < 64; q++) atomicAdd(&g_G[i_own * D_LAT + jb + q], acc[q]);
    if (tid < D_LAT) atomicAdd(&g_s[tid], s_loc);
}

// --------------------------- BN stats from Gram --------------------------------
__global__ void __launch_bounds__(256) stats_kernel(const float* __restrict__ W,
                                                    const float* __restrict__ bias) {
    __shared__ float Gs[D_LAT][65];
    __shared__ float ws[8][D_LAT];
    __shared__ float ss[D_LAT];

    const int tid = threadIdx.x;
    const int wrp = tid >> 5, lane = tid & 31;
    const int c0 = blockIdx.x * 8;
    const int c  = c0 + wrp;

    for (int idx = tid; idx < 8 * D_LAT; idx += 256) {
        const int cc = idx & 7, i = idx >> 3;
        ws[cc][i] = W[(size_t)i * D_IN + c0 + cc];
    }
    if (tid < D_LAT) ss[tid] = g_s[tid];

    float tpart[4] = {0.0f, 0.0f, 0.0f, 0.0f};
    for (int half = 0; half < 2; half++) {
        __syncthreads();
        for (int idx = tid; idx < D_LAT * 64; idx += 256) {
            const int i = idx >> 6, jj = idx & 63;
            Gs[i][jj] = g_G[i * D_LAT + half * 64 + jj];
        }
        __syncthreads();
#pragma unroll
        for (int ii = 0; ii < 4; ii++) {
            const int i = lane + ii * 32;
            float t = tpart[ii];
            const float* wr = &ws[wrp][half * 64];
#pragma unroll
            for (int jj = 0; jj < 64; jj++) t = __fmaf_rn(Gs[i][jj], wr[jj], t);
            tpart[ii] = t;
        }
    }

    float u = 0.0f, sw = 0.0f;
#pragma unroll
    for (int ii = 0; ii < 4; ii++) {
        const int i = lane + ii * 32;
        const float wi = ws[wrp][i];
        u  = __fmaf_rn(wi, tpart[ii], u);
        sw = __fmaf_rn(ss[i], wi, sw);
    }
#pragma unroll
    for (int o = 16; o > 0; o >>= 1) {
        u  += __shfl_xor_sync(0xffffffffu, u, o);
        sw += __shfl_xor_sync(0xffffffffu, sw, o);
    }
    if (lane == 0) {
        const float b   = bias[c];
        const float mu  = sw * (1.0f / (float)N_SPOTS) + b;
        const float eh2 = (u + 2.0f * b * sw) * (1.0f / (float)N_SPOTS) + b * b;
        const float var = eh2 - mu * mu;
        g_mu[c] = mu;
        g_rs[c] = 1.0f / sqrtf(var + BN_EPS);
    }
}

// --------------------- GEMM: hybrid tensor(bf16x3) + FFMA(fp32) ----------------
// de_feat = ELU(BN(z @ W + b)) [10000 x 3000], K=128.
// N-tile 128 = 72 tensor cols (warps 0-3, legacy mma 3x bf16 split)
//            + 56 FFMA cols   (warps 4-7, exact fp32)  -> both pipes busy.
// Last N-tile (bx=23): 56 FFMA cols only.

__device__ __forceinline__ void mma_bf16(float* d, const uint32_t* a, const uint32_t* b) {
    asm volatile(
        "mma.sync.aligned.m16n8k16.row.col.f32.bf16.bf16.f32 "
        "{%0,%1,%2,%3}, {%4,%5,%6,%7}, {%8,%9}, {%0,%1,%2,%3};"
        : "+f"(d[0]), "+f"(d[1]), "+f"(d[2]), "+f"(d[3])
        : "r"(a[0]), "r"(a[1]), "r"(a[2]), "r"(a[3]), "r"(b[0]), "r"(b[1]));
}

#define NT    72
#define NF    56
#define ASTR  20     // uint32 per A row: 0-7 hi kpairs, 8-15 lo, 4 pad
#define BSTR  72     // uint32 per B kpair-row (72 cols, conflict-free frags)
#define A32S  132    // floats per A32 k-row
#define B32S  60     // floats per B32 k-row

// dynamic smem offsets (bytes)
#define OFF_ABF 0                          // [2][128][ASTR] u32 = 20480
#define OFF_BBF 20480                      // [2][16][BSTR]  u32 = 9216
#define OFF_A32 29696                      // [2][16][A32S]  f32 = 16896
#define OFF_B32 46592                      // [2][16][B32S]  f32 = 7680
#define GEMM_SMEM 54272

__global__ void __launch_bounds__(256) gemm_kernel(const float* __restrict__ z,
                                                   const float* __restrict__ W,
                                                   const float* __restrict__ bias,
                                                   const float* __restrict__ gamma,
                                                   const float* __restrict__ beta,
                                                   float* __restrict__ de_out) {
    extern __shared__ char sm[];
    uint32_t* abf = (uint32_t*)(sm + OFF_ABF);
    uint32_t* bbf = (uint32_t*)(sm + OFF_BBF);
    float*    a32 = (float*)(sm + OFF_A32);
    float*    b32 = (float*)(sm + OFF_B32);
#define ABF(buf, r, w)  abf[((buf) * 128 + (r)) * ASTR + (w)]
#define BBF(buf, kr, n) bbf[((buf) * 16 + (kr)) * BSTR + (n)]
#define A32(buf, k, m)  a32[((buf) * 16 + (k)) * A32S + (m)]
#define B32(buf, k, n)  b32[((buf) * 16 + (k)) * B32S + (n)]

    const int tid  = threadIdx.x;
    const int wid  = tid >> 5;
    const int lane = tid & 31;
    const int bx   = blockIdx.x;
    const int bm   = blockIdx.y * 128;
    const bool last  = (bx == D_IN / 128);          // 23
    const int tcol0  = bx * 128;
    const int fcol0  = last ? (D_IN - NF) : (tcol0 + NT);

    // ---- loader roles (all 256 threads) ----
    const int arow_l = tid & 127;
    const int ahalf  = tid >> 7;
    const int arow   = min(bm + arow_l, N_SPOTS - 1);
    const uint32_t* zh_row = g_zh + (size_t)arow * 64;
    const uint32_t* zl_row = g_zl + (size_t)arow * 64;
    // B bf16: tid<144: n=tid>>1, kq=tid&1
    const int bbn   = tid >> 1;
    const int bkq   = tid & 1;
    const int bn_g  = min(tcol0 + bbn, D_IN - 1);   // clamped (last tile unused)
    // A fp32: e in {tid, tid+256}: row=e>>2, kq=e&3
    const int ar0 = tid >> 2, akq0 = tid & 3;
    const int ar1 = (tid + 256) >> 2, akq1 = tid & 3;
    const int arow0 = min(bm + ar0, N_SPOTS - 1);
    const int arow1 = min(bm + ar1, N_SPOTS - 1);
    // B fp32: tid<224: kk=tid/14, nq=tid%14
    const int bk32 = tid / 14;
    const int bq32 = tid - bk32 * 14;

    uint4  rah, ral, rbh, rbl;
    float4 rz0, rz1, rw;

#define LOADS(kslab)                                                            \
    {                                                                           \
        const int _kp0 = (kslab) >> 1;                                          \
        rah = *(const uint4*)&zh_row[_kp0 + ahalf * 4];                         \
        ral = *(const uint4*)&zl_row[_kp0 + ahalf * 4];                         \
        if (tid < 2 * NT) {                                                     \
            rbh = *(const uint4*)&g_bh[(size_t)bn_g * 64 + _kp0 + bkq * 4];     \
            rbl = *(const uint4*)&g_bl[(size_t)bn_g * 64 + _kp0 + bkq * 4];     \
        }                                                                       \
        rz0 = *(const float4*)&z[(size_t)arow0 * D_LAT + (kslab) + akq0 * 4];   \
        rz1 = *(const float4*)&z[(size_t)arow1 * D_LAT + (kslab) + akq1 * 4];   \
        if (tid < 224)                                                          \
            rw = *(const float4*)&W[(size_t)((kslab) + bk32) * D_IN + fcol0 + bq32 * 4]; \
    }

#define STORES(buf)                                                             \
    {                                                                           \
        *(uint4*)&ABF(buf, arow_l, ahalf * 4)     = rah;                        \
        *(uint4*)&ABF(buf, arow_l, 8 + ahalf * 4) = ral;                        \
        if (tid < 2 * NT) {                                                     \
            BBF(buf, bkq * 4 + 0, bbn) = rbh.x; BBF(buf, bkq * 4 + 1, bbn) = rbh.y; \
            BBF(buf, bkq * 4 + 2, bbn) = rbh.z; BBF(buf, bkq * 4 + 3, bbn) = rbh.w; \
            BBF(buf, 8 + bkq * 4 + 0, bbn) = rbl.x; BBF(buf, 8 + bkq * 4 + 1, bbn) = rbl.y; \
            BBF(buf, 8 + bkq * 4 + 2, bbn) = rbl.z; BBF(buf, 8 + bkq * 4 + 3, bbn) = rbl.w; \
        }                                                                       \
        A32(buf, akq0 * 4 + 0, ar0) = rz0.x; A32(buf, akq0 * 4 + 1, ar0) = rz0.y; \
        A32(buf, akq0 * 4 + 2, ar0) = rz0.z; A32(buf, akq0 * 4 + 3, ar0) = rz0.w; \
        A32(buf, akq1 * 4 + 0, ar1) = rz1.x; A32(buf, akq1 * 4 + 1, ar1) = rz1.y; \
        A32(buf, akq1 * 4 + 2, ar1) = rz1.z; A32(buf, akq1 * 4 + 3, ar1) = rz1.w; \
        if (tid < 224) *(float4*)&B32(buf, bk32, bq32 * 4) = rw;                \
    }

    // ---- accumulators ----
    // tensor warps (wid<4): warp rows [wid*32, wid*32+32), cols 0..71
    float tacc[2][9][4];
    // ffma warps (wid>=4): thread (tm, tn): rows tm*8..+7, cols tn*7..+6
    float facc[8][7];
    const int m0w = (wid & 3) * 32;
    const int tg  = lane & 3;
    const int gp  = lane >> 2;
    const int ft  = tid - 128;
    const int tm  = ft & 15;
    const int tn  = ft >> 4;

    if (wid < 4) {
#pragma unroll
        for (int mt = 0; mt < 2; mt++)
#pragma unroll
            for (int nt = 0; nt < 9; nt++)
#pragma unroll
                for (int q = 0; q < 4; q++) tacc[mt][nt][q] = 0.0f;
    } else {
#pragma unroll
        for (int p = 0; p < 8; p++)
#pragma unroll
            for (int q = 0; q < 7; q++) facc[p][q] = 0.0f;
    }

    LOADS(0);
    STORES(0);
    __syncthreads();

#pragma unroll 1
    for (int s = 0; s < 8; s++) {
        if (s < 7) LOADS((s + 1) * 16);
        const int cur = s & 1;

        if (wid < 4) {
            // ---- tensor compute: 9nt x 2mt x 3 splits ----
            uint32_t ah[2][4], al[2][4];
#pragma unroll
            for (int mt = 0; mt < 2; mt++) {
                const int mr = m0w + mt * 16;
                ah[mt][0] = ABF(cur, mr + gp,     tg);
                ah[mt][1] = ABF(cur, mr + gp + 8, tg);
                ah[mt][2] = ABF(cur, mr + gp,     tg + 4);
                ah[mt][3] = ABF(cur, mr + gp + 8, tg + 4);
                al[mt][0] = ABF(cur, mr + gp,     8 + tg);
                al[mt][1] = ABF(cur, mr + gp + 8, 8 + tg);
                al[mt][2] = ABF(cur, mr + gp,     8 + tg + 4);
                al[mt][3] = ABF(cur, mr + gp + 8, 8 + tg + 4);
            }
#pragma unroll
            for (int nt = 0; nt < 9; nt++) {
                const int nc = nt * 8 + gp;
                uint32_t bh[2] = { BBF(cur, tg, nc),     BBF(cur, tg + 4, nc) };
                uint32_t bl[2] = { BBF(cur, 8 + tg, nc), BBF(cur, 8 + tg + 4, nc) };
#pragma unroll
                for (int mt = 0; mt < 2; mt++) {
                    mma_bf16(tacc[mt][nt], ah[mt], bh);
                    mma_bf16(tacc[mt][nt], ah[mt], bl);
                    mma_bf16(tacc[mt][nt], al[mt], bh);
                }
            }
        } else {
            // ---- FFMA compute: 16 k-iters x 8x7 ----
#pragma unroll
            for (int kk = 0; kk < 16; kk++) {
                float a[8], b[7];
                *(float4*)&a[0] = *(const float4*)&A32(cur, kk, tm * 8);
                *(float4*)&a[4] = *(const float4*)&A32(cur, kk, tm * 8 + 4);
#pragma unroll
                for (int j = 0; j < 7; j++) b[j] = B32(cur, kk, tn * 7 + j);
#pragma unroll
                for (int p = 0; p < 8; p++)
#pragma unroll
                    for (int q = 0; q < 7; q++)
                        facc[p][q] = __fmaf_rn(a[p], b[q], facc[p][q]);
            }
        }

        if (s < 7) {
            STORES((s + 1) & 1);
            __syncthreads();
        }
    }

    // ---- epilogues: bias + BN + ELU ----
    if (wid < 4) {
        if (!last) {
#pragma unroll
            for (int nt = 0; nt < 9; nt++) {
                const int col = tcol0 + nt * 8 + tg * 2;
                const float bia0 = __ldg(&bias[col]),  bia1 = __ldg(&bias[col + 1]);
                const float mu0  = g_mu[col],          mu1  = g_mu[col + 1];
                const float rs0  = g_rs[col],          rs1  = g_rs[col + 1];
                const float ga0  = __ldg(&gamma[col]), ga1  = __ldg(&gamma[col + 1]);
                const float be0  = __ldg(&beta[col]),  be1  = __ldg(&beta[col + 1]);
#pragma unroll
                for (int mt = 0; mt < 2; mt++) {
#pragma unroll
                    for (int hf = 0; hf < 2; hf++) {
                        const int row = bm + m0w + mt * 16 + gp + hf * 8;
                        if (row >= N_SPOTS) continue;
                        const float h0 = tacc[mt][nt][hf * 2 + 0] + bia0;
                        const float h1 = tacc[mt][nt][hf * 2 + 1] + bia1;
                        float y0 = (h0 - mu0) * rs0 * ga0 + be0;
                        float y1 = (h1 - mu1) * rs1 * ga1 + be1;
                        y0 = (y0 > 0.0f) ? y0 : expm1f(y0);
                        y1 = (y1 > 0.0f) ? y1 : expm1f(y1);
                        *(float2*)&de_out[(size_t)row * D_IN + col] = make_float2(y0, y1);
                    }
                }
            }
        }
    } else {
        float bia[7], mu[7], rs[7], ga[7], be[7];
#pragma unroll
        for (int q = 0; q < 7; q++) {
            const int col = fcol0 + tn * 7 + q;
            bia[q] = __ldg(&bias[col]);
            mu[q]  = g_mu[col];
            rs[q]  = g_rs[col];
            ga[q]  = __ldg(&gamma[col]);
            be[q]  = __ldg(&beta[col]);
        }
#pragma unroll
        for (int p = 0; p < 8; p++) {
            const int row = bm + tm * 8 + p;
            if (row >= N_SPOTS) continue;
            float* dst = de_out + (size_t)row * D_IN + fcol0 + tn * 7;
#pragma unroll
            for (int q = 0; q < 7; q++) {
                const float h = facc[p][q] + bia[q];
                float y = (h - mu[q]) * rs[q] * ga[q] + be[q];
                y = (y > 0.0f) ? y : expm1f(y);
                dst[q] = y;
            }
        }
    }
}

// ------------------------------- launch ----------------------------------------
extern "C" void kernel_launch(void* const* d_in, const int* in_sizes, int n_in,
                              void* d_out, int out_size) {
    const float* x     = (const float*)d_in[0];   // [10000,128]
    const float* xn    = (const float*)d_in[1];   // [60000,128]
    const float* sp    = (const float*)d_in[2];   // [10000,2]
    const float* W     = (const float*)d_in[3];   // [128,3000]
    const float* bias  = (const float*)d_in[4];   // [3000]
    const float* gamma = (const float*)d_in[5];   // [3000]
    const float* beta  = (const float*)d_in[6];   // [3000]

    float* out = (float*)d_out;
    float* z_out  = out;                                   // [10000,128]
    float* de_out = out + (size_t)N_SPOTS * D_LAT;         // [10000,3000]
    float* hr_out = de_out + (size_t)N_SPOTS * D_IN;       // [10000,768]

    int* idx_ptr;   cudaGetSymbolAddress((void**)&idx_ptr, g_idx);
    void *cnt_p, *cur_p, *G_p, *s_p;
    cudaGetSymbolAddress(&cnt_p, g_cnt);
    cudaGetSymbolAddress(&cur_p, g_cur);
    cudaGetSymbolAddress(&G_p,   g_G);
    cudaGetSymbolAddress(&s_p,   g_s);

    cudaFuncSetAttribute(gemm_kernel, cudaFuncAttributeMaxDynamicSharedMemorySize, GEMM_SMEM);

    cudaMemsetAsync(cnt_p, 0, NCELLS * sizeof(int));
    cudaMemsetAsync(cur_p, 0, NCELLS * sizeof(int));
    cudaMemsetAsync(G_p,   0, D_LAT * D_LAT * sizeof(float));
    cudaMemsetAsync(s_p,   0, D_LAT * sizeof(float));

    split_w    <<<(D_IN * 64 + 255) / 256, 256>>>(W);
    knn_count  <<<(N_SPOTS + 255) / 256, 256>>>((const float2*)sp);
    knn_scan   <<<1, 32>>>();
    knn_scatter<<<(N_SPOTS + 255) / 256, 256>>>((const float2*)sp);
    knn_search <<<(N_SPOTS + 63) / 64, 64>>>(idx_ptr);
    agg_kernel <<<N_SPOTS, 128>>>(x, xn, z_out, hr_out);
    gram_kernel<<<GRAM_BLOCKS, 256>>>(z_out);
    stats_kernel<<<D_IN / 8, 256>>>(W, bias);
    gemm_kernel<<<dim3(D_IN / 128 + 1, (N_SPOTS + 127) / 128), 256, GEMM_SMEM>>>(
        z_out, W, bias, gamma, beta, de_out);
}

// round 9
// speedup vs baseline: 1.5520x; 1.5520x over previous
#include <cuda_runtime.h>
#include <cuda_bf16.h>
#include <math.h>
#include <stdint.h>

// Problem constants (fixed shapes)
#define N_SPOTS 10000
#define D_LAT   128
#define D_IN    3000
#define KNN_K   10
#define SCALE   6
#define BN_EPS  1e-4f

// KNN grid
#define GRID_D  40
#define CSZ     2.5f
#define INV_CSZ 0.4f
#define NCELLS  (GRID_D * GRID_D)
#define SLACK   0.5f

#define INF_F __int_as_float(0x7f800000)

// ---------------- scratch (device globals; no allocation allowed) -------------
__device__ int    g_idx[N_SPOTS * KNN_K];
__device__ int    g_cnt[NCELLS];
__device__ int    g_cur[NCELLS];
__device__ __align__(8)  int2   g_range[NCELLS];      // (start, count)
__device__ __align__(16) float4 g_sp4[N_SPOTS];       // (x, y, idx-bits, 0)
__device__ __align__(16) float g_G[D_LAT * D_LAT];    // Z^T Z
__device__ __align__(16) float g_s[D_LAT];            // col-sum of Z
__device__ __align__(16) float g_mu[D_IN];
__device__ __align__(16) float g_rs[D_IN];
// pre-split bf16 hi/lo operands (packed bf16x2 per k-pair), kpair-major for W
__device__ __align__(16) uint32_t g_zh[(size_t)N_SPOTS * 64];   // [row][kp]
__device__ __align__(16) uint32_t g_zl[(size_t)N_SPOTS * 64];
__device__ __align__(16) uint32_t g_bh[(size_t)64 * D_IN];      // [kp][n]
__device__ __align__(16) uint32_t g_bl[(size_t)64 * D_IN];

// lexicographic (d2, idx) compare: matches jax.lax.top_k stable tie-break
__device__ __forceinline__ bool lexless(float d1, int j1, float d2, int j2) {
    return (d1 < d2) || (d1 == d2 && j1 < j2);
}

__device__ __forceinline__ int cell_x(float x) {
    int c = (int)(x * INV_CSZ);
    return min(GRID_D - 1, max(0, c));
}

__device__ __forceinline__ void split_bf(float v, __nv_bfloat16& h, __nv_bfloat16& l) {
    h = __float2bfloat16_rn(v);
    l = __float2bfloat16_rn(v - __bfloat162float(h));
}

__device__ __forceinline__ uint32_t pack2(__nv_bfloat16 a, __nv_bfloat16 b) {
    __nv_bfloat162 t; t.x = a; t.y = b;     // .x = low 16 bits = lower-k element
    return *reinterpret_cast<uint32_t*>(&t);
}

// ----------------------------- KNN: build grid ---------------------------------
__global__ void knn_count(const float2* __restrict__ sp) {
    const int i = blockIdx.x * 256 + threadIdx.x;
    if (i >= N_SPOTS) return;
    const float2 s = sp[i];
    atomicAdd(&g_cnt[cell_x(s.y) * GRID_D + cell_x(s.x)], 1);
}

// single-warp exclusive scan over 1600 cells
__global__ void knn_scan() {
    const int lane = threadIdx.x;           // 32 threads
    const int CH = NCELLS / 32;             // 50
    const int base = lane * CH;
    int s = 0;
    for (int k = 0; k < CH; k++) s += g_cnt[base + k];
    int inc = s;
#pragma unroll
    for (int o = 1; o < 32; o <<= 1) {
        int v = __shfl_up_sync(0xffffffffu, inc, o);
        if (lane >= o) inc += v;
    }
    int run = inc - s;
    for (int k = 0; k < CH; k++) {
        const int c = g_cnt[base + k];
        g_range[base + k] = make_int2(run, c);
        run += c;
    }
}

__global__ void knn_scatter(const float2* __restrict__ sp) {
    const int i = blockIdx.x * 256 + threadIdx.x;
    if (i >= N_SPOTS) return;
    const float2 s = sp[i];
    const int c = cell_x(s.y) * GRID_D + cell_x(s.x);
    const int dst = g_range[c].x + atomicAdd(&g_cur[c], 1);
    g_sp4[dst] = make_float4(s.x, s.y, __int_as_float(i), 0.0f);
}

// ----------------------------- KNN: ring search --------------------------------
// d2 BIT-EXACT vs reference (XLA lowers the K=2 dot without fma):
//   sq = rn(rn(x*x) + rn(y*y));  dot = rn(rn(xi*xj) + rn(yi*yj))
//   d2 = rn(rn(sqi + sqj) - 2*dot)
// Cell points are batch-loaded into registers (independent LDG.128s, MLP~6)
// before the sequential compare/update chain, to hide L2 latency.
#define CBATCH 8
__device__ __forceinline__ void proc_cell(int c, int i, float mx, float my, float sqi,
                                          float* dd, int* jj,
                                          float& wd, int& wj, int& ws) {
    const int2 rg = g_range[c];
    int t = rg.x;
    const int t1 = rg.x + rg.y;
    while (t < t1) {
        const int nb = min(t1 - t, CBATCH);
        float4 buf[CBATCH];
#pragma unroll
        for (int u = 0; u < CBATCH; u++)
            if (u < nb) buf[u] = __ldg(&g_sp4[t + u]);
#pragma unroll
        for (int u = 0; u < CBATCH; u++) {
            if (u >= nb) continue;
            const float4 s = buf[u];
            const int j = __float_as_int(s.z);
            if (j == i) continue;
            const float sqj = __fadd_rn(__fmul_rn(s.x, s.x), __fmul_rn(s.y, s.y));
            const float dot = __fadd_rn(__fmul_rn(mx, s.x), __fmul_rn(my, s.y));
            const float d2  = __fadd_rn(__fadd_rn(sqi, sqj), __fmul_rn(-2.0f, dot));
            if (lexless(d2, j, wd, wj)) {
#pragma unroll
                for (int k = 0; k < KNN_K; k++) if (k == ws) { dd[k] = d2; jj[k] = j; }
                wd = dd[0]; wj = jj[0]; ws = 0;
#pragma unroll
                for (int k = 1; k < KNN_K; k++)
                    if (lexless(wd, wj, dd[k], jj[k])) { wd = dd[k]; wj = jj[k]; ws = k; }
            }
        }
        t += nb;
    }
}

__global__ void knn_search(int* __restrict__ idx_out) {
    const int p = blockIdx.x * 64 + threadIdx.x;
    if (p >= N_SPOTS) return;
    const float4 me = g_sp4[p];
    const int i = __float_as_int(me.z);
    const float sqi = __fadd_rn(__fmul_rn(me.x, me.x), __fmul_rn(me.y, me.y));
    const int cx = cell_x(me.x), cy = cell_x(me.y);

    float dd[KNN_K]; int jj[KNN_K];
#pragma unroll
    for (int k = 0; k < KNN_K; k++) { dd[k] = INF_F; jj[k] = 0x7fffffff; }
    float wd = INF_F; int wj = 0x7fffffff; int ws = 0;

    for (int R = 0; R <= GRID_D; R++) {
        if (R >= 2) {
            const float b = (float)(R - 1) * CSZ;
            if (wd + SLACK < b * b) break;
        }
        const int x0 = max(0, cx - R), x1 = min(GRID_D - 1, cx + R);
        const int y0 = max(0, cy - R), y1 = min(GRID_D - 1, cy + R);
        for (int yy = y0; yy <= y1; yy++) {
            if (yy == cy - R || yy == cy + R) {
                for (int xx = x0; xx <= x1; xx++)
                    proc_cell(yy * GRID_D + xx, i, me.x, me.y, sqi, dd, jj, wd, wj, ws);
            } else {
                if (cx - R >= 0)     proc_cell(yy * GRID_D + cx - R, i, me.x, me.y, sqi, dd, jj, wd, wj, ws);
                if (cx + R < GRID_D) proc_cell(yy * GRID_D + cx + R, i, me.x, me.y, sqi, dd, jj, wd, wj, ws);
            }
        }
    }
#pragma unroll
    for (int k = 0; k < KNN_K; k++) idx_out[i * KNN_K + k] = jj[k];
}

// --------------------------- aggregation (+ z bf16 split) ----------------------
__global__ void agg_kernel(const float* __restrict__ x,
                           const float* __restrict__ xn,
                           float* __restrict__ z_out,
                           float* __restrict__ hr_out) {
    const int i   = blockIdx.x;
    const int tid = threadIdx.x;          // 0..127
    const int lane = tid & 31, wrp = tid >> 5;

    __shared__ int   nb[KNN_K];
    __shared__ float red[4][KNN_K];
    __shared__ float neg_mean[KNN_K];

    if (tid < KNN_K) nb[tid] = g_idx[i * KNN_K + tid];
    __syncthreads();

    const float xi = x[(size_t)i * D_LAT + tid];
    float xv[KNN_K];
    float fd[KNN_K];
#pragma unroll
    for (int k = 0; k < KNN_K; k++) {
        const float v = x[(size_t)nb[k] * D_LAT + tid];
        xv[k] = v;
        const float d = v - xi;
        fd[k] = d * d;
    }
#pragma unroll
    for (int k = 0; k < KNN_K; k++) {
        float v = fd[k];
#pragma unroll
        for (int o = 16; o > 0; o >>= 1) v += __shfl_xor_sync(0xffffffffu, v, o);
        if (lane == 0) red[wrp][k] = v;
    }
    __syncthreads();
    if (tid < KNN_K) {
        const float s = red[0][tid] + red[1][tid] + red[2][tid] + red[3][tid];
        neg_mean[tid] = -(s * (1.0f / 128.0f));
    }
    __syncthreads();

    float m = neg_mean[0];
#pragma unroll
    for (int k = 1; k < KNN_K; k++) m = fmaxf(m, neg_mean[k]);
    float e[KNN_K], se = 0.0f;
#pragma unroll
    for (int k = 0; k < KNN_K; k++) { e[k] = expf(neg_mean[k] - m); se += e[k]; }
    float w[KNN_K];
#pragma unroll
    for (int k = 0; k < KNN_K; k++) w[k] = e[k] / se;

    float acc = 0.0f;
#pragma unroll
    for (int k = 0; k < KNN_K; k++) acc = __fmaf_rn(w[k], xv[k], acc);
    z_out[(size_t)i * D_LAT + tid] = acc;

    // bf16 hi/lo split of z, packed per k-pair (even lane packs tid & tid+1)
    const float accn = __shfl_down_sync(0xffffffffu, acc, 1);
    if ((tid & 1) == 0) {
        __nv_bfloat16 h0, l0, h1, l1;
        split_bf(acc,  h0, l0);
        split_bf(accn, h1, l1);
        g_zh[(size_t)i * 64 + (tid >> 1)] = pack2(h0, h1);
        g_zl[(size_t)i * 64 + (tid >> 1)] = pack2(l0, l1);
    }

#pragma unroll
    for (int s = 0; s < SCALE; s++) {
        float a = 0.0f;
#pragma unroll
        for (int k = 0; k < KNN_K; k++)
            a = __fmaf_rn(w[k], xn[((size_t)s * N_SPOTS + nb[k]) * D_LAT + tid], a);
        hr_out[(size_t)i * (SCALE * D_LAT) + s * D_LAT + tid] = a;
    }
}

// --------------------------- W bf16 split (kpair-major) ------------------------
__global__ void split_w(const float* __restrict__ W) {
    const int idx = blockIdx.x * 256 + threadIdx.x;     // kp * D_IN + n
    if (idx >= 64 * D_IN) return;
    const int kp = idx / D_IN, n = idx - kp * D_IN;
    const float v0 = W[(size_t)(2 * kp)     * D_IN + n];
    const float v1 = W[(size_t)(2 * kp + 1) * D_IN + n];
    __nv_bfloat16 h0, l0, h1, l1;
    split_bf(v0, h0, l0);
    split_bf(v1, h1, l1);
    g_bh[idx] = pack2(h0, h1);
    g_bl[idx] = pack2(l0, l1);
}

// --------------------------- Gram: G = Z^T Z, s = colsum(Z) --------------------
#define GRAM_BLOCKS 80
__global__ void __launch_bounds__(256) gram_kernel(const float* __restrict__ z) {
    __shared__ float zrow[D_LAT];
    const int tid = threadIdx.x;
    const int i_own = tid >> 1;
    const int jb    = (tid & 1) * 64;

    float acc[64];
#pragma unroll
    for (int q = 0; q < 64; q++) acc[q] = 0.0f;
    float s_loc = 0.0f;

    for (int m = blockIdx.x; m < N_SPOTS; m += GRAM_BLOCKS) {
        if (tid < D_LAT) zrow[tid] = z[(size_t)m * D_LAT + tid];
        __syncthreads();
        const float zi = zrow[i_own];
#pragma unroll
        for (int q = 0; q < 64; q++) acc[q] = __fmaf_rn(zi, zrow[jb + q], acc[q]);
        if (tid < D_LAT) s_loc += zrow[tid];
        __syncthreads();
    }
#pragma unroll
    for (int q = 0; q < 64; q++) atomicAdd(&g_G[i_own * D_LAT + jb + q], acc[q]);
    if (tid < D_LAT) atomicAdd(&g_s[tid], s_loc);
}

// --------------------------- BN stats from Gram --------------------------------
__global__ void __launch_bounds__(256) stats_kernel(const float* __restrict__ W,
                                                    const float* __restrict__ bias) {
    __shared__ float Gs[D_LAT][65];
    __shared__ float ws[8][D_LAT];
    __shared__ float ss[D_LAT];

    const int tid = threadIdx.x;
    const int wrp = tid >> 5, lane = tid & 31;
    const int c0 = blockIdx.x * 8;
    const int c  = c0 + wrp;

    for (int idx = tid; idx < 8 * D_LAT; idx += 256) {
        const int cc = idx & 7, i = idx >> 3;
        ws[cc][i] = W[(size_t)i * D_IN + c0 + cc];
    }
    if (tid < D_LAT) ss[tid] = g_s[tid];

    float tpart[4] = {0.0f, 0.0f, 0.0f, 0.0f};
    for (int half = 0; half < 2; half++) {
        __syncthreads();
        for (int idx = tid; idx < D_LAT * 64; idx += 256) {
            const int i = idx >> 6, jj = idx & 63;
            Gs[i][jj] = g_G[i * D_LAT + half * 64 + jj];
        }
        __syncthreads();
#pragma unroll
        for (int ii = 0; ii < 4; ii++) {
            const int i = lane + ii * 32;
            float t = tpart[ii];
            const float* wr = &ws[wrp][half * 64];
#pragma unroll
            for (int jj = 0; jj < 64; jj++) t = __fmaf_rn(Gs[i][jj], wr[jj], t);
            tpart[ii] = t;
        }
    }

    float u = 0.0f, sw = 0.0f;
#pragma unroll
    for (int ii = 0; ii < 4; ii++) {
        const int i = lane + ii * 32;
        const float wi = ws[wrp][i];
        u  = __fmaf_rn(wi, tpart[ii], u);
        sw = __fmaf_rn(ss[i], wi, sw);
    }
#pragma unroll
    for (int o = 16; o > 0; o >>= 1) {
        u  += __shfl_xor_sync(0xffffffffu, u, o);
        sw += __shfl_xor_sync(0xffffffffu, sw, o);
    }
    if (lane == 0) {
        const float b   = bias[c];
        const float mu  = sw * (1.0f / (float)N_SPOTS) + b;
        const float eh2 = (u + 2.0f * b * sw) * (1.0f / (float)N_SPOTS) + b * b;
        const float var = eh2 - mu * mu;
        g_mu[c] = mu;
        g_rs[c] = 1.0f / sqrtf(var + BN_EPS);
    }
}

// ------------------------------ GEMM (3x bf16 tensor cores) --------------------
// de_feat = ELU(BN(z @ W + b))  [10000 x 3000], K=128.
// Operands pre-split into bf16 hi/lo (packed kpairs) — no conversion in-loop.
// Block tile 128x128, k-slab 16, double buffered. Warp tile 32x64.
// Epilogue: bias + BN (mu/rs precomputed via Gram) + ELU, write de_out directly.

__device__ __forceinline__ void mma_bf16(float* d, const uint32_t* a, const uint32_t* b) {
    asm volatile(
        "mma.sync.aligned.m16n8k16.row.col.f32.bf16.bf16.f32 "
        "{%0,%1,%2,%3}, {%4,%5,%6,%7}, {%8,%9}, {%0,%1,%2,%3};"
        : "+f"(d[0]), "+f"(d[1]), "+f"(d[2]), "+f"(d[3])
        : "r"(a[0]), "r"(a[1]), "r"(a[2]), "r"(a[3]), "r"(b[0]), "r"(b[1]));
}

#define GM 128
#define GN 128
#define GK 16
#define ASTR 20    // uint32 per A row: words 0..7 hi (kpairs), 8..15 lo, 4 pad
#define BSTR 136   // uint32 per B kpair row: 128 n + 8 pad

__global__ void __launch_bounds__(256) gemm_kernel(const float* __restrict__ bias,
                                                   const float* __restrict__ gamma,
                                                   const float* __restrict__ beta,
                                                   float* __restrict__ de_out) {
    __shared__ __align__(16) uint32_t As[2][GM][ASTR];   // [buf][m][kpair(hi:0-7, lo:8-15)]
    __shared__ __align__(16) uint32_t Bs[2][16][BSTR];   // [buf][kpair(hi:0-7, lo:8-15)][n]

    const int bm  = blockIdx.y * GM;
    const int bn  = blockIdx.x * GN;
    const int tid = threadIdx.x;
    const int lane = tid & 31;
    const int wrp  = tid >> 5;
    const int tg   = lane & 3;     // threadID in quad
    const int gp   = lane >> 2;    // groupID
    const int m0w  = (wrp & 3) * 32;   // warp row offset in tile
    const int n0w  = (wrp >> 2) * 64;  // warp col offset in tile

    // --- global load indices ---
    const int arow_l = tid & 127;       // A row within tile
    const int ahalf  = tid >> 7;        // kpairs 0..3 or 4..7 of slab
    const int arow   = min(bm + arow_l, N_SPOTS - 1);
    const int bkp    = tid >> 5;        // B kpair within slab (0..7)
    const int bn4    = (tid & 31) * 4;  // B col within tile
    const int bcol   = min(bn + bn4, D_IN - 4);

    const uint32_t* zh_row = g_zh + (size_t)arow * 64;
    const uint32_t* zl_row = g_zl + (size_t)arow * 64;

    uint4 rah, ral, rbh, rbl;
    rah = *(const uint4*)&zh_row[ahalf * 4];
    ral = *(const uint4*)&zl_row[ahalf * 4];
    rbh = *(const uint4*)&g_bh[(size_t)bkp * D_IN + bcol];
    rbl = *(const uint4*)&g_bl[(size_t)bkp * D_IN + bcol];

    float acc[2][8][4];
#pragma unroll
    for (int mt = 0; mt < 2; mt++)
#pragma unroll
        for (int nt = 0; nt < 8; nt++)
#pragma unroll
            for (int q = 0; q < 4; q++) acc[mt][nt][q] = 0.0f;

#define STS_AB(buf)                                          \
    {                                                        \
        *(uint4*)&As[buf][arow_l][ahalf * 4]     = rah;      \
        *(uint4*)&As[buf][arow_l][8 + ahalf * 4] = ral;      \
        *(uint4*)&Bs[buf][bkp][bn4]              = rbh;      \
        *(uint4*)&Bs[buf][8 + bkp][bn4]          = rbl;      \
    }

    STS_AB(0);
    __syncthreads();

#pragma unroll 1
    for (int s = 0; s < D_LAT / GK; s++) {
        if (s < D_LAT / GK - 1) {
            const int kp0 = (s + 1) * 8;     // kpair base of next slab
            rah = *(const uint4*)&zh_row[kp0 + ahalf * 4];
            ral = *(const uint4*)&zl_row[kp0 + ahalf * 4];
            rbh = *(const uint4*)&g_bh[(size_t)(kp0 + bkp) * D_IN + bcol];
            rbl = *(const uint4*)&g_bl[(size_t)(kp0 + bkp) * D_IN + bcol];
        }
        const int cur = s & 1;

        uint32_t ah[2][4], al[2][4];
#pragma unroll
        for (int mt = 0; mt < 2; mt++) {
            const int mr = m0w + mt * 16;
            ah[mt][0] = As[cur][mr + gp][tg];
            ah[mt][1] = As[cur][mr + gp + 8][tg];
            ah[mt][2] = As[cur][mr + gp][tg + 4];
            ah[mt][3] = As[cur][mr + gp + 8][tg + 4];
            al[mt][0] = As[cur][mr + gp][8 + tg];
            al[mt][1] = As[cur][mr + gp + 8][8 + tg];
            al[mt][2] = As[cur][mr + gp][8 + tg + 4];
            al[mt][3] = As[cur][mr + gp + 8][8 + tg + 4];
        }

#pragma unroll
        for (int nt = 0; nt < 8; nt++) {
            const int nc = n0w + nt * 8 + gp;
            uint32_t bh[2] = { Bs[cur][tg][nc],     Bs[cur][tg + 4][nc] };
            uint32_t bl[2] = { Bs[cur][8 + tg][nc], Bs[cur][8 + tg + 4][nc] };
#pragma unroll
            for (int mt = 0; mt < 2; mt++) {
                mma_bf16(acc[mt][nt], ah[mt], bh);   // hi*hi
                mma_bf16(acc[mt][nt], ah[mt], bl);   // hi*lo
                mma_bf16(acc[mt][nt], al[mt], bh);   // lo*hi
            }
        }

        if (s < D_LAT / GK - 1) {
            STS_AB((s + 1) & 1);
            __syncthreads();
        }
    }

    // ---- epilogue: bias + BN + ELU, write de_out directly ----
#pragma unroll
    for (int nt = 0; nt < 8; nt++) {
        const int col = bn + n0w + nt * 8 + tg * 2;
        if (col >= D_IN) continue;          // col even, D_IN even -> col+1 also valid
        const float bia0 = __ldg(&bias[col]),  bia1 = __ldg(&bias[col + 1]);
        const float mu0  = g_mu[col],          mu1  = g_mu[col + 1];
        const float rs0  = g_rs[col],          rs1  = g_rs[col + 1];
        const float ga0  = __ldg(&gamma[col]), ga1  = __ldg(&gamma[col + 1]);
        const float be0  = __ldg(&beta[col]),  be1  = __ldg(&beta[col + 1]);
#pragma unroll
        for (int mt = 0; mt < 2; mt++) {
#pragma unroll
            for (int hf = 0; hf < 2; hf++) {
                const int row = bm + m0w + mt * 16 + gp + hf * 8;
                if (row >= N_SPOTS) continue;
                const float h0 = acc[mt][nt][hf * 2 + 0] + bia0;
                const float h1 = acc[mt][nt][hf * 2 + 1] + bia1;
                float y0 = (h0 - mu0) * rs0 * ga0 + be0;
                float y1 = (h1 - mu1) * rs1 * ga1 + be1;
                y0 = (y0 > 0.0f) ? y0 : expm1f(y0);
                y1 = (y1 > 0.0f) ? y1 : expm1f(y1);
                *(float2*)&de_out[(size_t)row * D_IN + col] = make_float2(y0, y1);
            }
        }
    }
}

// ------------------------------- launch ----------------------------------------
extern "C" void kernel_launch(void* const* d_in, const int* in_sizes, int n_in,
                              void* d_out, int out_size) {
    const float* x     = (const float*)d_in[0];   // [10000,128]
    const float* xn    = (const float*)d_in[1];   // [60000,128]
    const float* sp    = (const float*)d_in[2];   // [10000,2]
    const float* W     = (const float*)d_in[3];   // [128,3000]
    const float* bias  = (const float*)d_in[4];   // [3000]
    const float* gamma = (const float*)d_in[5];   // [3000]
    const float* beta  = (const float*)d_in[6];   // [3000]

    float* out = (float*)d_out;
    float* z_out  = out;                                   // [10000,128]
    float* de_out = out + (size_t)N_SPOTS * D_LAT;         // [10000,3000]
    float* hr_out = de_out + (size_t)N_SPOTS * D_IN;       // [10000,768]

    int* idx_ptr;   cudaGetSymbolAddress((void**)&idx_ptr, g_idx);
    void *cnt_p, *cur_p, *G_p, *s_p;
    cudaGetSymbolAddress(&cnt_p, g_cnt);
    cudaGetSymbolAddress(&cur_p, g_cur);
    cudaGetSymbolAddress(&G_p,   g_G);
    cudaGetSymbolAddress(&s_p,   g_s);

    cudaMemsetAsync(cnt_p, 0, NCELLS * sizeof(int));
    cudaMemsetAsync(cur_p, 0, NCELLS * sizeof(int));
    cudaMemsetAsync(G_p,   0, D_LAT * D_LAT * sizeof(float));
    cudaMemsetAsync(s_p,   0, D_LAT * sizeof(float));

    split_w    <<<(64 * D_IN + 255) / 256, 256>>>(W);
    knn_count  <<<(N_SPOTS + 255) / 256, 256>>>((const float2*)sp);
    knn_scan   <<<1, 32>>>();
    knn_scatter<<<(N_SPOTS + 255) / 256, 256>>>((const float2*)sp);
    knn_search <<<(N_SPOTS + 63) / 64, 64>>>(idx_ptr);
    agg_kernel <<<N_SPOTS, 128>>>(x, xn, z_out, hr_out);
    gram_kernel<<<GRAM_BLOCKS, 256>>>(z_out);
    stats_kernel<<<D_IN / 8, 256>>>(W, bias);
    gemm_kernel<<<dim3((D_IN + GN - 1) / GN, (N_SPOTS + GM - 1) / GM), 256>>>(
        bias, gamma, beta, de_out);
}

// round 10
// speedup vs baseline: 1.6407x; 1.0572x over previous
#include <cuda_runtime.h>
#include <cuda_bf16.h>
#include <math.h>
#include <stdint.h>

// Problem constants (fixed shapes)
#define N_SPOTS 10000
#define D_LAT   128
#define D_IN    3000
#define KNN_K   10
#define SCALE   6
#define BN_EPS  1e-4f

// KNN grid
#define GRID_D  40
#define CSZ     2.5f
#define INV_CSZ 0.4f
#define NCELLS  (GRID_D * GRID_D)
#define SLACK   0.5f

#define INF_F __int_as_float(0x7f800000)

// ---------------- scratch (device globals; no allocation allowed) -------------
__device__ int    g_idx[N_SPOTS * KNN_K];
__device__ int    g_cnt[NCELLS];
__device__ int    g_cur[NCELLS];
__device__ __align__(8)  int2   g_range[NCELLS];      // (start, count)
__device__ __align__(16) float4 g_sp4[N_SPOTS];       // (x, y, idx-bits, 0)
__device__ __align__(16) float g_G[D_LAT * D_LAT];    // Z^T Z
__device__ __align__(16) float g_s[D_LAT];            // col-sum of Z
__device__ __align__(16) float g_mu[D_IN];
__device__ __align__(16) float g_rs[D_IN];
// pre-split bf16 hi/lo operands (packed bf16x2 per k-pair), kpair-major for W
__device__ __align__(16) uint32_t g_zh[(size_t)N_SPOTS * 64];   // [row][kp]
__device__ __align__(16) uint32_t g_zl[(size_t)N_SPOTS * 64];
__device__ __align__(16) uint32_t g_bh[(size_t)64 * D_IN];      // [kp][n]
__device__ __align__(16) uint32_t g_bl[(size_t)64 * D_IN];

// lexicographic (d2, idx) compare: matches jax.lax.top_k stable tie-break
__device__ __forceinline__ bool lexless(float d1, int j1, float d2, int j2) {
    return (d1 < d2) || (d1 == d2 && j1 < j2);
}

__device__ __forceinline__ int cell_x(float x) {
    int c = (int)(x * INV_CSZ);
    return min(GRID_D - 1, max(0, c));
}

__device__ __forceinline__ void split_bf(float v, __nv_bfloat16& h, __nv_bfloat16& l) {
    h = __float2bfloat16_rn(v);
    l = __float2bfloat16_rn(v - __bfloat162float(h));
}

__device__ __forceinline__ uint32_t pack2(__nv_bfloat16 a, __nv_bfloat16 b) {
    __nv_bfloat162 t; t.x = a; t.y = b;     // .x = low 16 bits = lower-k element
    return *reinterpret_cast<uint32_t*>(&t);
}

// --------------------------- zero all scratch (1 launch) ------------------------
__global__ void zero_scratch() {
    const int i = blockIdx.x * 256 + threadIdx.x;
    if (i < NCELLS) { g_cnt[i] = 0; g_cur[i] = 0; }
    if (i < D_LAT)  g_s[i] = 0.0f;
    if (i < D_LAT * D_LAT) g_G[i] = 0.0f;
}

// ----------------------------- KNN: build grid ---------------------------------
__global__ void knn_count(const float2* __restrict__ sp) {
    const int i = blockIdx.x * 256 + threadIdx.x;
    if (i >= N_SPOTS) return;
    const float2 s = sp[i];
    atomicAdd(&g_cnt[cell_x(s.y) * GRID_D + cell_x(s.x)], 1);
}

// single-warp exclusive scan over 1600 cells
__global__ void knn_scan() {
    const int lane = threadIdx.x;           // 32 threads
    const int CH = NCELLS / 32;             // 50
    const int base = lane * CH;
    int s = 0;
    for (int k = 0; k < CH; k++) s += g_cnt[base + k];
    int inc = s;
#pragma unroll
    for (int o = 1; o < 32; o <<= 1) {
        int v = __shfl_up_sync(0xffffffffu, inc, o);
        if (lane >= o) inc += v;
    }
    int run = inc - s;
    for (int k = 0; k < CH; k++) {
        const int c = g_cnt[base + k];
        g_range[base + k] = make_int2(run, c);
        run += c;
    }
}

__global__ void knn_scatter(const float2* __restrict__ sp) {
    const int i = blockIdx.x * 256 + threadIdx.x;
    if (i >= N_SPOTS) return;
    const float2 s = sp[i];
    const int c = cell_x(s.y) * GRID_D + cell_x(s.x);
    const int dst = g_range[c].x + atomicAdd(&g_cur[c], 1);
    g_sp4[dst] = make_float4(s.x, s.y, __int_as_float(i), 0.0f);
}

// ----------------------------- KNN: ring search --------------------------------
// d2 BIT-EXACT vs reference (XLA lowers the K=2 dot without fma):
//   sq = rn(rn(x*x) + rn(y*y));  dot = rn(rn(xi*xj) + rn(yi*yj))
//   d2 = rn(rn(sqi + sqj) - 2*dot)
// Cell ranges live in smem (coalesced preload). Row-contiguous cells are merged
// into single spans (sorted array is contiguous in x within a y-row). Points are
// batch-loaded into registers (independent LDG.128s) to hide L2 latency.
#define CBATCH 8
__device__ __forceinline__ void proc_span(const int2* __restrict__ sr, int ca, int cb,
                                          int i, float mx, float my, float sqi,
                                          float* dd, int* jj,
                                          float& wd, int& wj, int& ws) {
    const int2 ra = sr[ca];
    const int2 rb = sr[cb];
    int t = ra.x;
    const int t1 = rb.x + rb.y;
    while (t < t1) {
        const int nb = min(t1 - t, CBATCH);
        float4 buf[CBATCH];
#pragma unroll
        for (int u = 0; u < CBATCH; u++)
            if (u < nb) buf[u] = __ldg(&g_sp4[t + u]);
#pragma unroll
        for (int u = 0; u < CBATCH; u++) {
            if (u >= nb) continue;
            const float4 s = buf[u];
            const int j = __float_as_int(s.z);
            if (j == i) continue;
            const float sqj = __fadd_rn(__fmul_rn(s.x, s.x), __fmul_rn(s.y, s.y));
            const float dot = __fadd_rn(__fmul_rn(mx, s.x), __fmul_rn(my, s.y));
            const float d2  = __fadd_rn(__fadd_rn(sqi, sqj), __fmul_rn(-2.0f, dot));
            if (lexless(d2, j, wd, wj)) {
#pragma unroll
                for (int k = 0; k < KNN_K; k++) if (k == ws) { dd[k] = d2; jj[k] = j; }
                wd = dd[0]; wj = jj[0]; ws = 0;
#pragma unroll
                for (int k = 1; k < KNN_K; k++)
                    if (lexless(wd, wj, dd[k], jj[k])) { wd = dd[k]; wj = jj[k]; ws = k; }
            }
        }
        t += nb;
    }
}

__global__ void __launch_bounds__(64) knn_search(int* __restrict__ idx_out) {
    __shared__ int2 srange[NCELLS];
    for (int t = threadIdx.x; t < NCELLS; t += 64)
        srange[t] = g_range[t];
    __syncthreads();

    const int p = blockIdx.x * 64 + threadIdx.x;
    if (p >= N_SPOTS) return;
    const float4 me = g_sp4[p];
    const int i = __float_as_int(me.z);
    const float sqi = __fadd_rn(__fmul_rn(me.x, me.x), __fmul_rn(me.y, me.y));
    const int cx = cell_x(me.x), cy = cell_x(me.y);

    float dd[KNN_K]; int jj[KNN_K];
#pragma unroll
    for (int k = 0; k < KNN_K; k++) { dd[k] = INF_F; jj[k] = 0x7fffffff; }
    float wd = INF_F; int wj = 0x7fffffff; int ws = 0;

    for (int R = 0; R <= GRID_D; R++) {
        if (R >= 2) {
            const float b = (float)(R - 1) * CSZ;
            if (wd + SLACK < b * b) break;
        }
        const int x0 = max(0, cx - R), x1 = min(GRID_D - 1, cx + R);
        const int y0 = max(0, cy - R), y1 = min(GRID_D - 1, cy + R);
        for (int yy = y0; yy <= y1; yy++) {
            if (yy == cy - R || yy == cy + R) {
                // full row of the ring: contiguous cells -> one span
                proc_span(srange, yy * GRID_D + x0, yy * GRID_D + x1,
                          i, me.x, me.y, sqi, dd, jj, wd, wj, ws);
            } else {
                if (cx - R >= 0)
                    proc_span(srange, yy * GRID_D + cx - R, yy * GRID_D + cx - R,
                              i, me.x, me.y, sqi, dd, jj, wd, wj, ws);
                if (cx + R < GRID_D)
                    proc_span(srange, yy * GRID_D + cx + R, yy * GRID_D + cx + R,
                              i, me.x, me.y, sqi, dd, jj, wd, wj, ws);
            }
        }
    }
#pragma unroll
    for (int k = 0; k < KNN_K; k++) idx_out[i * KNN_K + k] = jj[k];
}

// --------------------------- aggregation (+ z bf16 split) ----------------------
__global__ void agg_kernel(const float* __restrict__ x,
                           const float* __restrict__ xn,
                           float* __restrict__ z_out,
                           float* __restrict__ hr_out) {
    const int i   = blockIdx.x;
    const int tid = threadIdx.x;          // 0..127
    const int lane = tid & 31, wrp = tid >> 5;

    __shared__ int   nb[KNN_K];
    __shared__ float red[4][KNN_K];
    __shared__ float neg_mean[KNN_K];

    if (tid < KNN_K) nb[tid] = g_idx[i * KNN_K + tid];
    __syncthreads();

    const float xi = x[(size_t)i * D_LAT + tid];
    float xv[KNN_K];
    float fd[KNN_K];
#pragma unroll
    for (int k = 0; k < KNN_K; k++) {
        const float v = x[(size_t)nb[k] * D_LAT + tid];
        xv[k] = v;
        const float d = v - xi;
        fd[k] = d * d;
    }
#pragma unroll
    for (int k = 0; k < KNN_K; k++) {
        float v = fd[k];
#pragma unroll
        for (int o = 16; o > 0; o >>= 1) v += __shfl_xor_sync(0xffffffffu, v, o);
        if (lane == 0) red[wrp][k] = v;
    }
    __syncthreads();
    if (tid < KNN_K) {
        const float s = red[0][tid] + red[1][tid] + red[2][tid] + red[3][tid];
        neg_mean[tid] = -(s * (1.0f / 128.0f));
    }
    __syncthreads();

    float m = neg_mean[0];
#pragma unroll
    for (int k = 1; k < KNN_K; k++) m = fmaxf(m, neg_mean[k]);
    float e[KNN_K], se = 0.0f;
#pragma unroll
    for (int k = 0; k < KNN_K; k++) { e[k] = expf(neg_mean[k] - m); se += e[k]; }
    float w[KNN_K];
#pragma unroll
    for (int k = 0; k < KNN_K; k++) w[k] = e[k] / se;

    float acc = 0.0f;
#pragma unroll
    for (int k = 0; k < KNN_K; k++) acc = __fmaf_rn(w[k], xv[k], acc);
    z_out[(size_t)i * D_LAT + tid] = acc;

    // bf16 hi/lo split of z, packed per k-pair (even lane packs tid & tid+1)
    const float accn = __shfl_down_sync(0xffffffffu, acc, 1);
    if ((tid & 1) == 0) {
        __nv_bfloat16 h0, l0, h1, l1;
        split_bf(acc,  h0, l0);
        split_bf(accn, h1, l1);
        g_zh[(size_t)i * 64 + (tid >> 1)] = pack2(h0, h1);
        g_zl[(size_t)i * 64 + (tid >> 1)] = pack2(l0, l1);
    }

#pragma unroll
    for (int s = 0; s < SCALE; s++) {
        float a = 0.0f;
#pragma unroll
        for (int k = 0; k < KNN_K; k++)
            a = __fmaf_rn(w[k], xn[((size_t)s * N_SPOTS + nb[k]) * D_LAT + tid], a);
        hr_out[(size_t)i * (SCALE * D_LAT) + s * D_LAT + tid] = a;
    }
}

// --------------------------- W bf16 split (kpair-major) ------------------------
__global__ void split_w(const float* __restrict__ W) {
    const int idx = blockIdx.x * 256 + threadIdx.x;     // kp * D_IN + n
    if (idx >= 64 * D_IN) return;
    const int kp = idx / D_IN, n = idx - kp * D_IN;
    const float v0 = W[(size_t)(2 * kp)     * D_IN + n];
    const float v1 = W[(size_t)(2 * kp + 1) * D_IN + n];
    __nv_bfloat16 h0, l0, h1, l1;
    split_bf(v0, h0, l0);
    split_bf(v1, h1, l1);
    g_bh[idx] = pack2(h0, h1);
    g_bl[idx] = pack2(l0, l1);
}

// --------------------------- Gram: G = Z^T Z, s = colsum(Z) --------------------
#define GRAM_BLOCKS 80
__global__ void __launch_bounds__(256) gram_kernel(const float* __restrict__ z) {
    __shared__ float zrow[D_LAT];
    const int tid = threadIdx.x;
    const int i_own = tid >> 1;
    const int jb    = (tid & 1) * 64;

    float acc[64];
#pragma unroll
    for (int q = 0; q < 64; q++) acc[q] = 0.0f;
    float s_loc = 0.0f;

    for (int m = blockIdx.x; m < N_SPOTS; m += GRAM_BLOCKS) {
        if (tid < D_LAT) zrow[tid] = z[(size_t)m * D_LAT + tid];
        __syncthreads();
        const float zi = zrow[i_own];
#pragma unroll
        for (int q = 0; q < 64; q++) acc[q] = __fmaf_rn(zi, zrow[jb + q], acc[q]);
        if (tid < D_LAT) s_loc += zrow[tid];
        __syncthreads();
    }
#pragma unroll
    for (int q = 0; q < 64; q++) atomicAdd(&g_G[i_own * D_LAT + jb + q], acc[q]);
    if (tid < D_LAT) atomicAdd(&g_s[tid], s_loc);
}

// --------------------------- BN stats from Gram --------------------------------
__global__ void __launch_bounds__(256) stats_kernel(const float* __restrict__ W,
                                                    const float* __restrict__ bias) {
    __shared__ float Gs[D_LAT][65];
    __shared__ float ws[8][D_LAT];
    __shared__ float ss[D_LAT];

    const int tid = threadIdx.x;
    const int wrp = tid >> 5, lane = tid & 31;
    const int c0 = blockIdx.x * 8;
    const int c  = c0 + wrp;

    for (int idx = tid; idx < 8 * D_LAT; idx += 256) {
        const int cc = idx & 7, i = idx >> 3;
        ws[cc][i] = W[(size_t)i * D_IN + c0 + cc];
    }
    if (tid < D_LAT) ss[tid] = g_s[tid];

    float tpart[4] = {0.0f, 0.0f, 0.0f, 0.0f};
    for (int half = 0; half < 2; half++) {
        __syncthreads();
        for (int idx = tid; idx < D_LAT * 64; idx += 256) {
            const int i = idx >> 6, jj = idx & 63;
            Gs[i][jj] = g_G[i * D_LAT + half * 64 + jj];
        }
        __syncthreads();
#pragma unroll
        for (int ii = 0; ii < 4; ii++) {
            const int i = lane + ii * 32;
            float t = tpart[ii];
            const float* wr = &ws[wrp][half * 64];
#pragma unroll
            for (int jj = 0; jj < 64; jj++) t = __fmaf_rn(Gs[i][jj], wr[jj], t);
            tpart[ii] = t;
        }
    }

    float u = 0.0f, sw = 0.0f;
#pragma unroll
    for (int ii = 0; ii < 4; ii++) {
        const int i = lane + ii * 32;
        const float wi = ws[wrp][i];
        u  = __fmaf_rn(wi, tpart[ii], u);
        sw = __fmaf_rn(ss[i], wi, sw);
    }
#pragma unroll
    for (int o = 16; o > 0; o >>= 1) {
        u  += __shfl_xor_sync(0xffffffffu, u, o);
        sw += __shfl_xor_sync(0xffffffffu, sw, o);
    }
    if (lane == 0) {
        const float b   = bias[c];
        const float mu  = sw * (1.0f / (float)N_SPOTS) + b;
        const float eh2 = (u + 2.0f * b * sw) * (1.0f / (float)N_SPOTS) + b * b;
        const float var = eh2 - mu * mu;
        g_mu[c] = mu;
        g_rs[c] = 1.0f / sqrtf(var + BN_EPS);
    }
}

// ------------------------------ GEMM (3x bf16 tensor cores) --------------------
// de_feat = ELU(BN(z @ W + b))  [10000 x 3000], K=128.
// Operands pre-split into bf16 hi/lo (packed kpairs) — no conversion in-loop.
// Block tile 128x128, k-slab 16, double buffered. Warp tile 32x64.
// Epilogue: bias + BN (mu/rs precomputed via Gram) + ELU, write de_out directly.

__device__ __forceinline__ void mma_bf16(float* d, const uint32_t* a, const uint32_t* b) {
    asm volatile(
        "mma.sync.aligned.m16n8k16.row.col.f32.bf16.bf16.f32 "
        "{%0,%1,%2,%3}, {%4,%5,%6,%7}, {%8,%9}, {%0,%1,%2,%3};"
        : "+f"(d[0]), "+f"(d[1]), "+f"(d[2]), "+f"(d[3])
        : "r"(a[0]), "r"(a[1]), "r"(a[2]), "r"(a[3]), "r"(b[0]), "r"(b[1]));
}

#define GM 128
#define GN 128
#define GK 16
#define ASTR 20    // uint32 per A row: words 0..7 hi (kpairs), 8..15 lo, 4 pad
#define BSTR 136   // uint32 per B kpair row: 128 n + 8 pad

__global__ void __launch_bounds__(256) gemm_kernel(const float* __restrict__ bias,
                                                   const float* __restrict__ gamma,
                                                   const float* __restrict__ beta,
                                                   float* __restrict__ de_out) {
    __shared__ __align__(16) uint32_t As[2][GM][ASTR];   // [buf][m][kpair(hi:0-7, lo:8-15)]
    __shared__ __align__(16) uint32_t Bs[2][16][BSTR];   // [buf][kpair(hi:0-7, lo:8-15)][n]

    const int bm  = blockIdx.y * GM;
    const int bn  = blockIdx.x * GN;
    const int tid = threadIdx.x;
    const int lane = tid & 31;
    const int wrp  = tid >> 5;
    const int tg   = lane & 3;     // threadID in quad
    const int gp   = lane >> 2;    // groupID
    const int m0w  = (wrp & 3) * 32;   // warp row offset in tile
    const int n0w  = (wrp >> 2) * 64;  // warp col offset in tile

    // --- global load indices ---
    const int arow_l = tid & 127;       // A row within tile
    const int ahalf  = tid >> 7;        // kpairs 0..3 or 4..7 of slab
    const int arow   = min(bm + arow_l, N_SPOTS - 1);
    const int bkp    = tid >> 5;        // B kpair within slab (0..7)
    const int bn4    = (tid & 31) * 4;  // B col within tile
    const int bcol   = min(bn + bn4, D_IN - 4);

    const uint32_t* zh_row = g_zh + (size_t)arow * 64;
    const uint32_t* zl_row = g_zl + (size_t)arow * 64;

    uint4 rah, ral, rbh, rbl;
    rah = *(const uint4*)&zh_row[ahalf * 4];
    ral = *(const uint4*)&zl_row[ahalf * 4];
    rbh = *(const uint4*)&g_bh[(size_t)bkp * D_IN + bcol];
    rbl = *(const uint4*)&g_bl[(size_t)bkp * D_IN + bcol];

    float acc[2][8][4];
#pragma unroll
    for (int mt = 0; mt < 2; mt++)
#pragma unroll
        for (int nt = 0; nt < 8; nt++)
#pragma unroll
            for (int q = 0; q < 4; q++) acc[mt][nt][q] = 0.0f;

#define STS_AB(buf)                                          \
    {                                                        \
        *(uint4*)&As[buf][arow_l][ahalf * 4]     = rah;      \
        *(uint4*)&As[buf][arow_l][8 + ahalf * 4] = ral;      \
        *(uint4*)&Bs[buf][bkp][bn4]              = rbh;      \
        *(uint4*)&Bs[buf][8 + bkp][bn4]          = rbl;      \
    }

    STS_AB(0);
    __syncthreads();

#pragma unroll 1
    for (int s = 0; s < D_LAT / GK; s++) {
        if (s < D_LAT / GK - 1) {
            const int kp0 = (s + 1) * 8;     // kpair base of next slab
            rah = *(const uint4*)&zh_row[kp0 + ahalf * 4];
            ral = *(const uint4*)&zl_row[kp0 + ahalf * 4];
            rbh = *(const uint4*)&g_bh[(size_t)(kp0 + bkp) * D_IN + bcol];
            rbl = *(const uint4*)&g_bl[(size_t)(kp0 + bkp) * D_IN + bcol];
        }
        const int cur = s & 1;

        uint32_t ah[2][4], al[2][4];
#pragma unroll
        for (int mt = 0; mt < 2; mt++) {
            const int mr = m0w + mt * 16;
            ah[mt][0] = As[cur][mr + gp][tg];
            ah[mt][1] = As[cur][mr + gp + 8][tg];
            ah[mt][2] = As[cur][mr + gp][tg + 4];
            ah[mt][3] = As[cur][mr + gp + 8][tg + 4];
            al[mt][0] = As[cur][mr + gp][8 + tg];
            al[mt][1] = As[cur][mr + gp + 8][8 + tg];
            al[mt][2] = As[cur][mr + gp][8 + tg + 4];
            al[mt][3] = As[cur][mr + gp + 8][8 + tg + 4];
        }

#pragma unroll
        for (int nt = 0; nt < 8; nt++) {
            const int nc = n0w + nt * 8 + gp;
            uint32_t bh[2] = { Bs[cur][tg][nc],     Bs[cur][tg + 4][nc] };
            uint32_t bl[2] = { Bs[cur][8 + tg][nc], Bs[cur][8 + tg + 4][nc] };
#pragma unroll
            for (int mt = 0; mt < 2; mt++) {
                mma_bf16(acc[mt][nt], ah[mt], bh);   // hi*hi
                mma_bf16(acc[mt][nt], ah[mt], bl);   // hi*lo
                mma_bf16(acc[mt][nt], al[mt], bh);   // lo*hi
            }
        }

        if (s < D_LAT / GK - 1) {
            STS_AB((s + 1) & 1);
            __syncthreads();
        }
    }

    // ---- epilogue: bias + BN + ELU, write de_out directly ----
#pragma unroll
    for (int nt = 0; nt < 8; nt++) {
        const int col = bn + n0w + nt * 8 + tg * 2;
        if (col >= D_IN) continue;          // col even, D_IN even -> col+1 also valid
        const float bia0 = __ldg(&bias[col]),  bia1 = __ldg(&bias[col + 1]);
        const float mu0  = g_mu[col],          mu1  = g_mu[col + 1];
        const float rs0  = g_rs[col],          rs1  = g_rs[col + 1];
        const float ga0  = __ldg(&gamma[col]), ga1  = __ldg(&gamma[col + 1]);
        const float be0  = __ldg(&beta[col]),  be1  = __ldg(&beta[col + 1]);
#pragma unroll
        for (int mt = 0; mt < 2; mt++) {
#pragma unroll
            for (int hf = 0; hf < 2; hf++) {
                const int row = bm + m0w + mt * 16 + gp + hf * 8;
                if (row >= N_SPOTS) continue;
                const float h0 = acc[mt][nt][hf * 2 + 0] + bia0;
                const float h1 = acc[mt][nt][hf * 2 + 1] + bia1;
                float y0 = (h0 - mu0) * rs0 * ga0 + be0;
                float y1 = (h1 - mu1) * rs1 * ga1 + be1;
                y0 = (y0 > 0.0f) ? y0 : expm1f(y0);
                y1 = (y1 > 0.0f) ? y1 : expm1f(y1);
                *(float2*)&de_out[(size_t)row * D_IN + col] = make_float2(y0, y1);
            }
        }
    }
}

// ------------------------------- launch ----------------------------------------
extern "C" void kernel_launch(void* const* d_in, const int* in_sizes, int n_in,
                              void* d_out, int out_size) {
    const float* x     = (const float*)d_in[0];   // [10000,128]
    const float* xn    = (const float*)d_in[1];   // [60000,128]
    const float* sp    = (const float*)d_in[2];   // [10000,2]
    const float* W     = (const float*)d_in[3];   // [128,3000]
    const float* bias  = (const float*)d_in[4];   // [3000]
    const float* gamma = (const float*)d_in[5];   // [3000]
    const float* beta  = (const float*)d_in[6];   // [3000]

    float* out = (float*)d_out;
    float* z_out  = out;                                   // [10000,128]
    float* de_out = out + (size_t)N_SPOTS * D_LAT;         // [10000,3000]
    float* hr_out = de_out + (size_t)N_SPOTS * D_IN;       // [10000,768]

    int* idx_ptr;   cudaGetSymbolAddress((void**)&idx_ptr, g_idx);

    // Launch order chosen so ncu (-s 5 -c 1) profiles knn_search (launch #6).
    zero_scratch<<<(D_LAT * D_LAT + 255) / 256, 256>>>();
    knn_count  <<<(N_SPOTS + 255) / 256, 256>>>((const float2*)sp);
    knn_scan   <<<1, 32>>>();
    knn_scatter<<<(N_SPOTS + 255) / 256, 256>>>((const float2*)sp);
    split_w    <<<(64 * D_IN + 255) / 256, 256>>>(W);
    knn_search <<<(N_SPOTS + 63) / 64, 64>>>(idx_ptr);
    agg_kernel <<<N_SPOTS, 128>>>(x, xn, z_out, hr_out);
    gram_kernel<<<GRAM_BLOCKS, 256>>>(z_out);
    stats_kernel<<<D_IN / 8, 256>>>(W, bias);
    gemm_kernel<<<dim3((D_IN + GN - 1) / GN, (N_SPOTS + GM - 1) / GM), 256>>>(
        bias, gamma, beta, de_out);
}